// round 9
// baseline (speedup 1.0000x reference)
#include <cuda_runtime.h>
#include <cstdint>

// ---------------- problem constants ----------------
#define BATCH   16
#define SEQ     2048
#define INP     256
#define HID     1024
#define MAXNZ   64
#define NCTA    128
#define NTHR    256
#define HDEPTH  8                        // h0 ring depth (layer0 may run ahead)
#define OUT_MAIN (BATCH*SEQ*INP)        // 8388608
#define HT_ELEMS (2*BATCH*HID)          // 32768
#define SQRT10  3.1622776601683795f

// ---------------- device scratch (no allocs allowed) ----------------
__device__ float          g_xT[(size_t)SEQ*INP*BATCH];       // [t][j][b]
__device__ float          g_outsT[(size_t)SEQ*HID*BATCH];    // [t][i][b]  (h1 per step)
__device__ float          g_h0[HDEPTH][HID*BATCH];           // layer0 state ring
__device__ float          g_WT[HID*INP];                     // out_w transposed [i][o]
__device__ unsigned short g_idx[3][HID][MAXNZ];              // 0: ih0, 1: hh0, 2: hh1
__device__ float          g_val[3][HID][MAXNZ];
__device__ int            g_cnt[3][HID];
__device__ unsigned int   g_slotsA[64];                      // layer0 per-CTA phase
__device__ unsigned int   g_slotsB[64];                      // layer1 per-CTA phase

// ---------------- small helpers ----------------
__device__ __forceinline__ unsigned long long pk2(float lo, float hi) {
    unsigned long long r;
    asm("mov.b64 %0, {%1,%2};" : "=l"(r) : "f"(lo), "f"(hi));
    return r;
}
__device__ __forceinline__ void upk2(unsigned long long v, float& lo, float& hi) {
    asm("mov.b64 {%0,%1}, %2;" : "=f"(lo), "=f"(hi) : "l"(v));
}
__device__ __forceinline__ void fma2(unsigned long long& d, unsigned long long a, unsigned long long b) {
    asm("fma.rn.f32x2 %0, %1, %2, %3;" : "=l"(d) : "l"(a), "l"(b), "l"(d));
}
__device__ __forceinline__ unsigned ld_relax(const unsigned* p) {
    unsigned v;
    asm volatile("ld.relaxed.gpu.global.u32 %0, [%1];" : "=r"(v) : "l"(p) : "memory");
    return v;
}
__device__ __forceinline__ unsigned ld_acq(const unsigned* p) {
    unsigned v;
    asm volatile("ld.acquire.gpu.global.u32 %0, [%1];" : "=r"(v) : "l"(p) : "memory");
    return v;
}
__device__ __forceinline__ void st_rel(unsigned* p, unsigned v) {
    asm volatile("st.release.gpu.global.u32 [%0], %1;" :: "l"(p), "r"(v) : "memory");
}

// warp0 helper: all 64 slots of array s >= tgt. Relaxed poll; acquire confirm once.
// Call from threads 0..31 only, warp-uniform tgt.
__device__ __forceinline__ void poll64(const unsigned* s, unsigned tgt) {
    int l = threadIdx.x;      // 0..31
    for (;;) {
        unsigned a = ld_relax(s + l);
        unsigned c = ld_relax(s + l + 32);
        if (__all_sync(0xffffffffu, (a >= tgt) && (c >= tgt))) break;
    }
    ld_acq(s + l);
}

// ---------------- kernel: zero slots ----------------
__global__ void k_zero_slots() {
    if (threadIdx.x < 64) { g_slotsA[threadIdx.x] = 0u; g_slotsB[threadIdx.x] = 0u; }
}

// ---------------- kernel: transpose x [b][t][j] -> xT [t][j][b] ----------------
__global__ void k_xT(const float* __restrict__ x) {
    __shared__ float sm[INP * 17];
    int t = blockIdx.x;
    int tid = threadIdx.x;
    #pragma unroll
    for (int bb = 0; bb < BATCH; bb++) {
        sm[tid * 17 + bb] = x[(size_t)bb * SEQ * INP + (size_t)t * INP + tid];
    }
    __syncthreads();
    float* dst = g_xT + (size_t)t * (INP * BATCH);
    #pragma unroll
    for (int k = 0; k < 16; k++) {
        int f = k * 256 + tid;            // f = j*16 + b
        dst[f] = sm[(f >> 4) * 17 + (f & 15)];
    }
}

// ---------------- kernel: build CSR ----------------
__global__ void k_csr(const float* __restrict__ wih, const float* __restrict__ whh) {
    int warp = threadIdx.x >> 5;
    int lane = threadIdx.x & 31;
    int gr = blockIdx.x * 8 + warp;
    if (gr >= 3 * HID) return;
    int m = gr / HID;
    int row = gr % HID;
    const float* src;
    int ncol;
    if (m == 0) { src = wih + (size_t)row * INP; ncol = INP; }
    else        { src = whh + ((size_t)(m - 1) * HID + row) * HID; ncol = HID; }
    int base = 0;
    for (int c0 = 0; c0 < ncol; c0 += 32) {
        float w = src[c0 + lane];
        unsigned mask = __ballot_sync(0xffffffffu, w != 0.0f);
        if (w != 0.0f) {
            int pos = base + __popc(mask & ((1u << lane) - 1u));
            if (pos < MAXNZ) {
                g_idx[m][row][pos] = (unsigned short)(c0 + lane);
                g_val[m][row][pos] = w;
            }
        }
        base += __popc(mask);
    }
    int cnt = base < MAXNZ ? base : MAXNZ;
    int rcnt = (cnt + 3) & ~3;
    for (int p = cnt + lane; p < rcnt; p += 32) {
        g_idx[m][row][p] = 0;
        g_val[m][row][p] = 0.0f;
    }
    if (lane == 0) g_cnt[m][row] = rcnt;
}

// ---------------- kernel: transpose out_w ----------------
__global__ void k_wT(const float* __restrict__ ow) {
    __shared__ float tl[32][33];
    int i0 = blockIdx.x * 32, o0 = blockIdx.y * 32;
    int tx = threadIdx.x, ty = threadIdx.y;
    tl[ty][tx] = ow[(size_t)(o0 + ty) * HID + i0 + tx];
    __syncthreads();
    g_WT[(size_t)(i0 + ty) * INP + o0 + tx] = tl[tx][ty];
}

// ---------------- persistent recurrence kernel ----------------
// CTAs 0..63  : layer 0, neurons [cta*16, cta*16+16)
// CTAs 64..127: layer 1
// Per-CTA slot arrays (no contended single-address atomics); layer1 chases layer0.
__global__ void __launch_bounds__(NTHR, 1) k_rnn() {
    __shared__ unsigned short sIdxA[16][MAXNZ];
    __shared__ float          sValA[16][MAXNZ];
    __shared__ unsigned short sIdxB[16][MAXNZ];
    __shared__ float          sValB[16][MAXNZ];
    __shared__ int sCntA[16], sCntB[16];

    int cta = blockIdx.x;
    int layer = cta >> 6;
    int gc = cta & 63;                   // index within group
    int r0 = gc * 16;
    int mA = (layer == 0) ? 0 : 2;       // layer0: ih0 ; layer1: hh1

    for (int e = threadIdx.x; e < 16 * MAXNZ; e += NTHR) {
        int rr = e >> 6, kk = e & 63;
        sIdxA[rr][kk] = g_idx[mA][r0 + rr][kk];
        sValA[rr][kk] = g_val[mA][r0 + rr][kk];
        if (layer == 0) {
            sIdxB[rr][kk] = g_idx[1][r0 + rr][kk];   // hh0
            sValB[rr][kk] = g_val[1][r0 + rr][kk];
        }
    }
    if (threadIdx.x < 16) {
        sCntA[threadIdx.x] = g_cnt[mA][r0 + threadIdx.x];
        sCntB[threadIdx.x] = (layer == 0) ? g_cnt[1][r0 + threadIdx.x] : 0;
    }
    __syncthreads();

    int warp = threadIdx.x >> 5;
    int lane = threadIdx.x & 31;
    int il = 2 * warp + (lane >> 4);   // local neuron 0..15
    int b  = lane & 15;                // batch
    int i  = r0 + il;
    int cA = sCntA[il];
    int cB = sCntB[il];

    if (layer == 0) {
        // ---------------- layer 0 pipeline ----------------
        float ffx;
        {
            const float* xp = g_xT + b;
            float a0 = 0.0f, a1 = 0.0f;
            for (int k = 0; k < cA; k += 4) {
                int j0 = sIdxA[il][k], j1 = sIdxA[il][k+1], j2 = sIdxA[il][k+2], j3 = sIdxA[il][k+3];
                float v0 = sValA[il][k], v1 = sValA[il][k+1], v2 = sValA[il][k+2], v3 = sValA[il][k+3];
                a0 += v0 * __ldg(xp + (j0 << 4));
                a1 += v1 * __ldg(xp + (j1 << 4));
                a0 += v2 * __ldg(xp + (j2 << 4));
                a1 += v3 * __ldg(xp + (j3 << 4));
            }
            ffx = a0 + a1;
        }
        for (int t = 0; t < SEQ; t++) {
            if (t > 0) {
                if (threadIdx.x < 32) {
                    poll64(g_slotsA, (unsigned)t);                 // all h0(t-1) visible
                    if (t >= HDEPTH)
                        poll64(g_slotsB, (unsigned)(t - HDEPTH + 1)); // ring slot free
                }
                __syncthreads();
            }
            float acc0 = SQRT10 + ffx, acc1 = 0.0f;
            if (t > 0) {
                const float* hp = g_h0[(t - 1) & (HDEPTH - 1)] + b;
                for (int k = 0; k < cB; k += 4) {
                    int j0 = sIdxB[il][k], j1 = sIdxB[il][k+1], j2 = sIdxB[il][k+2], j3 = sIdxB[il][k+3];
                    float v0 = sValB[il][k], v1 = sValB[il][k+1], v2 = sValB[il][k+2], v3 = sValB[il][k+3];
                    acc0 += v0 * __ldcg(hp + (j0 << 4));
                    acc1 += v1 * __ldcg(hp + (j1 << 4));
                    acc0 += v2 * __ldcg(hp + (j2 << 4));
                    acc1 += v3 * __ldcg(hp + (j3 << 4));
                }
            }
            __stcg(&g_h0[t & (HDEPTH - 1)][i * 16 + b], fmaxf(acc0 + acc1, 0.0f));
            __syncthreads();
            if (threadIdx.x == 0) st_rel(&g_slotsA[gc], (unsigned)(t + 1));
            // prefetch ffx(t+1) AFTER release -> x DRAM latency off critical path
            if (t + 1 < SEQ) {
                const float* xp = g_xT + (size_t)(t + 1) * (INP * BATCH) + b;
                float a0 = 0.0f, a1 = 0.0f;
                for (int k = 0; k < cA; k += 4) {
                    int j0 = sIdxA[il][k], j1 = sIdxA[il][k+1], j2 = sIdxA[il][k+2], j3 = sIdxA[il][k+3];
                    float v0 = sValA[il][k], v1 = sValA[il][k+1], v2 = sValA[il][k+2], v3 = sValA[il][k+3];
                    a0 += v0 * __ldg(xp + (j0 << 4));
                    a1 += v1 * __ldg(xp + (j1 << 4));
                    a0 += v2 * __ldg(xp + (j2 << 4));
                    a1 += v3 * __ldg(xp + (j3 << 4));
                }
                ffx = a0 + a1;
            }
        }
    } else {
        // ---------------- layer 1 pipeline ----------------
        for (int t = 0; t < SEQ; t++) {
            float accR0 = 0.0f, accR1 = 0.0f;
            if (t > 0) {
                if (threadIdx.x < 32) poll64(g_slotsB, (unsigned)t);   // h1(t-1) visible
                __syncthreads();
                // gather recurrence while layer0 may still be finishing h0(t)
                const float* hp = g_outsT + (size_t)(t - 1) * (HID * BATCH) + b;
                for (int k = 0; k < cA; k += 4) {
                    int j0 = sIdxA[il][k], j1 = sIdxA[il][k+1], j2 = sIdxA[il][k+2], j3 = sIdxA[il][k+3];
                    float v0 = sValA[il][k], v1 = sValA[il][k+1], v2 = sValA[il][k+2], v3 = sValA[il][k+3];
                    accR0 += v0 * __ldcg(hp + (j0 << 4));
                    accR1 += v1 * __ldcg(hp + (j1 << 4));
                    accR0 += v2 * __ldcg(hp + (j2 << 4));
                    accR1 += v3 * __ldcg(hp + (j3 << 4));
                }
            }
            if (threadIdx.x < 32) poll64(g_slotsA, (unsigned)(t + 1));  // h0(t) visible
            __syncthreads();
            float acc0 = SQRT10 + accR0, acc1 = accR1;
            {
                const float* fp = g_h0[t & (HDEPTH - 1)] + b;
                for (int k = 0; k < cA; k += 4) {
                    int j0 = sIdxA[il][k], j1 = sIdxA[il][k+1], j2 = sIdxA[il][k+2], j3 = sIdxA[il][k+3];
                    float v0 = sValA[il][k], v1 = sValA[il][k+1], v2 = sValA[il][k+2], v3 = sValA[il][k+3];
                    acc0 += v0 * __ldcg(fp + (j0 << 4));
                    acc1 += v1 * __ldcg(fp + (j1 << 4));
                    acc0 += v2 * __ldcg(fp + (j2 << 4));
                    acc1 += v3 * __ldcg(fp + (j3 << 4));
                }
            }
            __stcg(&g_outsT[(size_t)t * (HID * BATCH) + i * 16 + b], fmaxf(acc0 + acc1, 0.0f));
            __syncthreads();
            if (threadIdx.x == 0) st_rel(&g_slotsB[gc], (unsigned)(t + 1));
        }
    }
}

// ---------------- projection: out[b][t][o] = sum_i h1[t][i][b]*W[o][i] + bias[o] ----------------
__global__ void __launch_bounds__(NTHR) k_proj(const float* __restrict__ ob, float* __restrict__ out) {
    __shared__ float sh[512 * BATCH];
    int t = blockIdx.x;
    int o = threadIdx.x;
    float bias = __ldg(ob + o);
    unsigned long long acc[8];
    #pragma unroll
    for (int j = 0; j < 8; j++) acc[j] = pk2(bias, bias);
    #pragma unroll
    for (int half = 0; half < 2; half++) {
        __syncthreads();
        const float* src = g_outsT + (size_t)t * (HID * BATCH) + half * (512 * BATCH);
        for (int e = threadIdx.x; e < 512 * BATCH; e += NTHR) sh[e] = src[e];
        __syncthreads();
        const float* wcol = g_WT + (size_t)(half * 512) * INP + o;
        #pragma unroll 2
        for (int i = 0; i < 512; i++) {
            float w = __ldg(wcol + (size_t)i * INP);
            unsigned long long wp = pk2(w, w);
            const unsigned long long* hp = (const unsigned long long*)(sh + i * BATCH);
            fma2(acc[0], hp[0], wp);
            fma2(acc[1], hp[1], wp);
            fma2(acc[2], hp[2], wp);
            fma2(acc[3], hp[3], wp);
            fma2(acc[4], hp[4], wp);
            fma2(acc[5], hp[5], wp);
            fma2(acc[6], hp[6], wp);
            fma2(acc[7], hp[7], wp);
        }
    }
    #pragma unroll
    for (int j = 0; j < 8; j++) {
        float lo, hi;
        upk2(acc[j], lo, hi);
        out[((size_t)(2 * j)     * SEQ + t) * INP + o] = lo;
        out[((size_t)(2 * j + 1) * SEQ + t) * INP + o] = hi;
    }
}

// ---------------- final hidden state h_T [l][b][i] ----------------
__global__ void k_ht(float* __restrict__ out) {
    int e = blockIdx.x * blockDim.x + threadIdx.x;
    if (e >= HT_ELEMS) return;
    int l = e / (BATCH * HID);
    int r = e % (BATCH * HID);
    int b = r / HID;
    int i = r % HID;
    float v;
    if (l == 0) v = g_h0[(SEQ - 1) & (HDEPTH - 1)][i * 16 + b];
    else        v = g_outsT[(size_t)(SEQ - 1) * (HID * BATCH) + i * 16 + b];
    out[(size_t)OUT_MAIN + e] = v;
}

// ---------------- launch ----------------
// NOTE: k_rnn placed 4th so ncu (-s 5 with 2 harness-internal launches ahead)
// captures it instead of k_wT. k_rnn depends only on zero/xT/csr; k_wT is
// needed only by k_proj, which launches after.
extern "C" void kernel_launch(void* const* d_in, const int* in_sizes, int n_in,
                              void* d_out, int out_size) {
    const float* x   = (const float*)d_in[0];
    const float* wih = (const float*)d_in[1];
    const float* whh = (const float*)d_in[2];
    const float* ow  = (const float*)d_in[3];
    const float* ob  = (const float*)d_in[4];
    float* out = (float*)d_out;

    k_zero_slots<<<1, 64>>>();
    k_xT<<<SEQ, 256>>>(x);
    k_csr<<<(3 * HID) / 8, 256>>>(wih, whh);
    k_rnn<<<NCTA, NTHR>>>();
    k_wT<<<dim3(HID / 32, INP / 32), dim3(32, 32)>>>(ow);
    k_proj<<<SEQ, NTHR>>>(ob, out);
    if (out_size >= OUT_MAIN + HT_ELEMS) {
        k_ht<<<(HT_ELEMS + 511) / 512, 512>>>(out);
    }
}

// round 11
// speedup vs baseline: 1.9501x; 1.9501x over previous
#include <cuda_runtime.h>
#include <cstdint>

// ---------------- problem constants ----------------
#define BATCH   16
#define SEQ     2048
#define INP     256
#define HID     1024
#define MAXNZ   64
#define NCTA    64
#define NTHR    288                      // 8 compute warps + 1 sync warp
#define NGRP    8                        // arrival counter groups
#define OUT_MAIN (BATCH*SEQ*INP)        // 8388608
#define HT_ELEMS (2*BATCH*HID)          // 32768
#define SQRT10  3.1622776601683795f

// ---------------- device scratch (no allocs allowed) ----------------
__device__ float          g_ffA[(size_t)SEQ*HID*BATCH];      // [t][i][b]  sqrt10 + Wih@x
__device__ float          g_outsT[(size_t)SEQ*HID*BATCH];    // [t][i][b]  h1 per step
__device__ float          g_h0[2][HID*BATCH];                // layer0 state ping-pong
__device__ float          g_WT[HID*INP];                     // out_w transposed [i][o]
__device__ unsigned short g_idx[3][HID][MAXNZ];              // 0: ih0, 1: hh0, 2: hh1
__device__ float          g_val[3][HID][MAXNZ];
__device__ int            g_cnt[3][HID];

struct __align__(256) Ctr { unsigned v; unsigned pad[63]; };  // 256B stride -> distinct L2 slices
__device__ Ctr g_ctr[NGRP];

// ---------------- small helpers ----------------
__device__ __forceinline__ unsigned long long pk2(float lo, float hi) {
    unsigned long long r;
    asm("mov.b64 %0, {%1,%2};" : "=l"(r) : "f"(lo), "f"(hi));
    return r;
}
__device__ __forceinline__ void upk2(unsigned long long v, float& lo, float& hi) {
    asm("mov.b64 {%0,%1}, %2;" : "=f"(lo), "=f"(hi) : "l"(v));
}
__device__ __forceinline__ void fma2(unsigned long long& d, unsigned long long a, unsigned long long b) {
    asm("fma.rn.f32x2 %0, %1, %2, %3;" : "=l"(d) : "l"(a), "l"(b), "l"(d));
}
__device__ __forceinline__ unsigned ld_relax(const unsigned* p) {
    unsigned v;
    asm volatile("ld.relaxed.gpu.global.u32 %0, [%1];" : "=r"(v) : "l"(p) : "memory");
    return v;
}
__device__ __forceinline__ unsigned ld_acq(const unsigned* p) {
    unsigned v;
    asm volatile("ld.acquire.gpu.global.u32 %0, [%1];" : "=r"(v) : "l"(p) : "memory");
    return v;
}
__device__ __forceinline__ void red_release(unsigned* p) {
    asm volatile("red.release.gpu.global.add.u32 [%0], %1;" :: "l"(p), "r"(1u) : "memory");
}

// ---------------- kernel: build CSR ----------------
// m=0: weight_ih[0] (1024x256), m=1: weight_hh[0], m=2: weight_hh[1]
__global__ void k_csr(const float* __restrict__ wih, const float* __restrict__ whh) {
    int warp = threadIdx.x >> 5;
    int lane = threadIdx.x & 31;
    int gr = blockIdx.x * 8 + warp;
    if (gr >= 3 * HID) return;
    int m = gr / HID;
    int row = gr % HID;
    const float* src;
    int ncol;
    if (m == 0) { src = wih + (size_t)row * INP; ncol = INP; }
    else        { src = whh + ((size_t)(m - 1) * HID + row) * HID; ncol = HID; }
    int base = 0;
    for (int c0 = 0; c0 < ncol; c0 += 32) {
        float w = src[c0 + lane];
        unsigned mask = __ballot_sync(0xffffffffu, w != 0.0f);
        if (w != 0.0f) {
            int pos = base + __popc(mask & ((1u << lane) - 1u));
            if (pos < MAXNZ) {
                g_idx[m][row][pos] = (unsigned short)(c0 + lane);
                g_val[m][row][pos] = w;
            }
        }
        base += __popc(mask);
    }
    int cnt = base < MAXNZ ? base : MAXNZ;
    int rcnt = (cnt + 3) & ~3;             // pad to multiple of 4 with zeros
    for (int p = cnt + lane; p < rcnt; p += 32) {
        g_idx[m][row][p] = 0;
        g_val[m][row][p] = 0.0f;
    }
    if (lane == 0) g_cnt[m][row] = rcnt;
}

// ---------------- kernel: feedforward precompute + counter zero ----------------
// ffA[t][i][b] = SQRT10 + sum_j wih0[i,j] * x[b,t,j]
// One CTA per t. x slice loaded directly (transposed into padded smem).
__global__ void __launch_bounds__(256) k_ff(const float* __restrict__ x) {
    __shared__ float sx[INP * 17];        // padded: sx[j*17 + b]
    int t = blockIdx.x;
    int tid = threadIdx.x;
    if (t == 0 && tid < NGRP) g_ctr[tid].v = 0u;   // zero barrier counters each replay
    #pragma unroll
    for (int bb = 0; bb < BATCH; bb++) {
        // threads 0..255 read x[bb][t][tid] (coalesced); store conflict-free (stride 17)
        sx[tid * 17 + bb] = x[(size_t)bb * SEQ * INP + (size_t)t * INP + tid];
    }
    __syncthreads();
    int rgrp = tid >> 4;                  // 0..15
    int b    = tid & 15;
    float* dst = g_ffA + (size_t)t * (HID * BATCH);
    for (int q = 0; q < HID / 16; q++) {
        int r = q * 16 + rgrp;
        int cnt = g_cnt[0][r];
        const unsigned short* ip = g_idx[0][r];
        const float* vp = g_val[0][r];
        float a0 = SQRT10, a1 = 0.0f;
        for (int k = 0; k < cnt; k += 4) {
            int j0 = ip[k], j1 = ip[k+1], j2 = ip[k+2], j3 = ip[k+3];
            float v0 = vp[k], v1 = vp[k+1], v2 = vp[k+2], v3 = vp[k+3];
            a0 += v0 * sx[j0 * 17 + b];
            a1 += v1 * sx[j1 * 17 + b];
            a0 += v2 * sx[j2 * 17 + b];
            a1 += v3 * sx[j3 * 17 + b];
        }
        dst[r * 16 + b] = a0 + a1;
    }
}

// ---------------- kernel: transpose out_w ----------------
__global__ void k_wT(const float* __restrict__ ow) {
    __shared__ float tl[32][33];
    int i0 = blockIdx.x * 32, o0 = blockIdx.y * 32;
    int tx = threadIdx.x, ty = threadIdx.y;
    tl[ty][tx] = ow[(size_t)(o0 + ty) * HID + i0 + tx];
    __syncthreads();
    g_WT[(size_t)(i0 + ty) * INP + o0 + tx] = tl[tx][ty];
}

// ---------------- persistent recurrence kernel ----------------
// 64 CTAs x 288 threads. CTA c owns rows [16c,16c+16) of BOTH layers.
// Warps 0-7: compute (one (i,b) element per layer per thread).
// Warp 8: sync only — arrive (red.release to ctr[cta&7]) + narrow poll (8 words).
// Phase p: h0(p) = relu(ffA(p) + Whh0 h0(p-1));  h1(p-1) = relu(sqrt10 + Whh1(h0(p-1)+h1(p-2))).
// All phase-p inputs were produced in phase p-1 -> one barrier per phase.
__global__ void __launch_bounds__(NTHR, 1) k_rnn() {
    __shared__ unsigned short sIdx0[16][MAXNZ];  // hh0
    __shared__ float          sVal0[16][MAXNZ];
    __shared__ unsigned short sIdx1[16][MAXNZ];  // hh1
    __shared__ float          sVal1[16][MAXNZ];
    __shared__ int sC[2][16];

    int cta = blockIdx.x;
    int r0 = cta * 16;

    for (int e = threadIdx.x; e < 16 * MAXNZ; e += NTHR) {
        int rr = e >> 6, kk = e & 63;
        sIdx0[rr][kk] = g_idx[1][r0 + rr][kk];
        sVal0[rr][kk] = g_val[1][r0 + rr][kk];
        sIdx1[rr][kk] = g_idx[2][r0 + rr][kk];
        sVal1[rr][kk] = g_val[2][r0 + rr][kk];
    }
    if (threadIdx.x < 32) {
        int m = threadIdx.x >> 4, rr = threadIdx.x & 15;
        sC[m][rr] = g_cnt[m + 1][r0 + rr];
    }
    __syncthreads();

    bool is_sync = (threadIdx.x >= 256);
    int warp = threadIdx.x >> 5;
    int lane = threadIdx.x & 31;
    int il = 2 * warp + (lane >> 4);     // 0..15 (compute warps only)
    int b  = lane & 15;
    int i  = r0 + il;
    int c0 = is_sync ? 0 : sC[0][il];
    int c1 = is_sync ? 0 : sC[1][il];

    float ffv = 0.0f;
    if (!is_sync) ffv = __ldcg(&g_ffA[(size_t)0 * (HID * BATCH) + i * 16 + b]);

    for (int p = 0; p <= SEQ; p++) {
        const float* hprev = g_h0[(p + 1) & 1] + b;   // h0(p-1)

        if (!is_sync) {
            // ---- layer 0: h0(p) ----
            if (p < SEQ) {
                float acc0 = ffv, acc1 = 0.0f;
                if (p > 0) {
                    for (int k = 0; k < c0; k += 4) {
                        int j0 = sIdx0[il][k], j1 = sIdx0[il][k+1], j2 = sIdx0[il][k+2], j3 = sIdx0[il][k+3];
                        float v0 = sVal0[il][k], v1 = sVal0[il][k+1], v2 = sVal0[il][k+2], v3 = sVal0[il][k+3];
                        acc0 += v0 * __ldcg(hprev + (j0 << 4));
                        acc1 += v1 * __ldcg(hprev + (j1 << 4));
                        acc0 += v2 * __ldcg(hprev + (j2 << 4));
                        acc1 += v3 * __ldcg(hprev + (j3 << 4));
                    }
                }
                __stcg(&g_h0[p & 1][i * 16 + b], fmaxf(acc0 + acc1, 0.0f));
            }
            // ---- layer 1: h1(p-1) ----
            if (p >= 1) {
                int t1 = p - 1;
                float acc0 = SQRT10, acc1 = 0.0f;
                if (t1 > 0) {
                    const float* h1p = g_outsT + (size_t)(t1 - 1) * (HID * BATCH) + b;
                    for (int k = 0; k < c1; k += 4) {
                        int j0 = sIdx1[il][k], j1 = sIdx1[il][k+1], j2 = sIdx1[il][k+2], j3 = sIdx1[il][k+3];
                        float v0 = sVal1[il][k], v1 = sVal1[il][k+1], v2 = sVal1[il][k+2], v3 = sVal1[il][k+3];
                        float s0 = __ldcg(hprev + (j0 << 4)) + __ldcg(h1p + (j0 << 4));
                        float s1 = __ldcg(hprev + (j1 << 4)) + __ldcg(h1p + (j1 << 4));
                        float s2 = __ldcg(hprev + (j2 << 4)) + __ldcg(h1p + (j2 << 4));
                        float s3 = __ldcg(hprev + (j3 << 4)) + __ldcg(h1p + (j3 << 4));
                        acc0 += v0 * s0;
                        acc1 += v1 * s1;
                        acc0 += v2 * s2;
                        acc1 += v3 * s3;
                    }
                } else {
                    for (int k = 0; k < c1; k += 4) {
                        int j0 = sIdx1[il][k], j1 = sIdx1[il][k+1], j2 = sIdx1[il][k+2], j3 = sIdx1[il][k+3];
                        float v0 = sVal1[il][k], v1 = sVal1[il][k+1], v2 = sVal1[il][k+2], v3 = sVal1[il][k+3];
                        acc0 += v0 * __ldcg(hprev + (j0 << 4));
                        acc1 += v1 * __ldcg(hprev + (j1 << 4));
                        acc0 += v2 * __ldcg(hprev + (j2 << 4));
                        acc1 += v3 * __ldcg(hprev + (j3 << 4));
                    }
                }
                __stcg(&g_outsT[(size_t)t1 * (HID * BATCH) + i * 16 + b], fmaxf(acc0 + acc1, 0.0f));
            }
        }

        __syncthreads();   // (A) phase-p stores done CTA-locally

        if (is_sync) {
            if (p < SEQ) {
                // release: makes this CTA's phase-p stores visible (CTA-hb via barrier A,
                // carried to gpu scope by the cumulative release)
                if (lane == 0) red_release(&g_ctr[cta & (NGRP - 1)].v);
                unsigned tgt = (unsigned)(NGRP * (p + 1));
                const unsigned* cp = &g_ctr[lane & (NGRP - 1)].v;
                for (;;) {
                    unsigned v = ld_relax(cp);
                    if (__all_sync(0xffffffffu, v >= tgt)) break;
                }
                ld_acq(cp);    // synchronizes-with the releases (monotonic counter)
            }
        } else {
            // window: stream the next feedforward value; latency hides under poll
            if (p + 1 < SEQ) {
                ffv = __ldcg(&g_ffA[(size_t)(p + 1) * (HID * BATCH) + i * 16 + b]);
            }
        }

        __syncthreads();   // (B) all phase-p results globally visible
    }
}

// ---------------- projection: out[b][t][o] = sum_i h1[t][i][b]*W[o][i] + bias[o] ----------------
__global__ void __launch_bounds__(256) k_proj(const float* __restrict__ ob, float* __restrict__ out) {
    __shared__ float sh[512 * BATCH];
    int t = blockIdx.x;
    int o = threadIdx.x;
    float bias = __ldg(ob + o);
    unsigned long long acc[8];
    #pragma unroll
    for (int j = 0; j < 8; j++) acc[j] = pk2(bias, bias);
    #pragma unroll
    for (int half = 0; half < 2; half++) {
        __syncthreads();
        const float* src = g_outsT + (size_t)t * (HID * BATCH) + half * (512 * BATCH);
        for (int e = threadIdx.x; e < 512 * BATCH; e += 256) sh[e] = src[e];
        __syncthreads();
        const float* wcol = g_WT + (size_t)(half * 512) * INP + o;
        #pragma unroll 2
        for (int i = 0; i < 512; i++) {
            float w = __ldg(wcol + (size_t)i * INP);
            unsigned long long wp = pk2(w, w);
            const unsigned long long* hp = (const unsigned long long*)(sh + i * BATCH);
            fma2(acc[0], hp[0], wp);
            fma2(acc[1], hp[1], wp);
            fma2(acc[2], hp[2], wp);
            fma2(acc[3], hp[3], wp);
            fma2(acc[4], hp[4], wp);
            fma2(acc[5], hp[5], wp);
            fma2(acc[6], hp[6], wp);
            fma2(acc[7], hp[7], wp);
        }
    }
    #pragma unroll
    for (int j = 0; j < 8; j++) {
        float lo, hi;
        upk2(acc[j], lo, hi);
        out[((size_t)(2 * j)     * SEQ + t) * INP + o] = lo;
        out[((size_t)(2 * j + 1) * SEQ + t) * INP + o] = hi;
    }
}

// ---------------- final hidden state h_T [l][b][i] ----------------
__global__ void k_ht(float* __restrict__ out) {
    int e = blockIdx.x * blockDim.x + threadIdx.x;
    if (e >= HT_ELEMS) return;
    int l = e / (BATCH * HID);
    int r = e % (BATCH * HID);
    int b = r / HID;
    int i = r % HID;
    float v;
    if (l == 0) v = g_h0[(SEQ - 1) & 1][i * 16 + b];
    else        v = g_outsT[(size_t)(SEQ - 1) * (HID * BATCH) + i * 16 + b];
    out[(size_t)OUT_MAIN + e] = v;
}

// ---------------- launch ----------------
// Order keeps k_rnn at overall launch index 5 (2 harness launches + csr, ff, wT)
// so ncu (-s 5 -c 1) profiles k_rnn.
extern "C" void kernel_launch(void* const* d_in, const int* in_sizes, int n_in,
                              void* d_out, int out_size) {
    const float* x   = (const float*)d_in[0];
    const float* wih = (const float*)d_in[1];
    const float* whh = (const float*)d_in[2];
    const float* ow  = (const float*)d_in[3];
    const float* ob  = (const float*)d_in[4];
    float* out = (float*)d_out;

    k_csr<<<(3 * HID) / 8, 256>>>(wih, whh);
    k_ff<<<SEQ, 256>>>(x);
    k_wT<<<dim3(HID / 32, INP / 32), dim3(32, 32)>>>(ow);
    k_rnn<<<NCTA, NTHR>>>();
    k_proj<<<SEQ, 256>>>(ob, out);
    if (out_size >= OUT_MAIN + HT_ELEMS) {
        k_ht<<<(HT_ELEMS + 511) / 512, 512>>>(out);
    }
}

// round 12
// speedup vs baseline: 2.2044x; 1.1304x over previous
#include <cuda_runtime.h>
#include <cstdint>

// ---------------- problem constants ----------------
#define BATCH   16
#define SEQ     2048
#define INP     256
#define HID     1024
#define MAXNZ   64
#define NCTA    128
#define NTHR    288                      // 8 compute warps + 1 sync warp
#define NGRP    8                        // sharded arrival counters per layer
#define HDEPTH  4                        // h0 ring depth
#define OUT_MAIN (BATCH*SEQ*INP)        // 8388608
#define HT_ELEMS (2*BATCH*HID)          // 32768
#define SQRT10  3.1622776601683795f

// ---------------- device scratch (no allocs allowed) ----------------
__device__ float          g_xT[(size_t)SEQ*INP*BATCH];       // [t][j][b]  33MB -> L2-resident
__device__ float          g_outsT[(size_t)SEQ*HID*BATCH];    // [t][i][b]  h1 per step
__device__ float          g_h0[HDEPTH][HID*BATCH];           // layer0 state ring
__device__ float          g_WT[HID*INP];                     // out_w transposed [i][o]
__device__ unsigned short g_idx[3][HID][MAXNZ];              // 0: ih0, 1: hh0, 2: hh1
__device__ float          g_val[3][HID][MAXNZ];
__device__ int            g_cnt[3][HID];

struct __align__(256) Ctr { unsigned v; unsigned pad[63]; }; // 256B stride
__device__ Ctr g_ctrA[NGRP];             // layer0 arrivals (8 CTAs each)
__device__ Ctr g_ctrB[NGRP];             // layer1 arrivals

// ---------------- small helpers ----------------
__device__ __forceinline__ unsigned long long pk2(float lo, float hi) {
    unsigned long long r;
    asm("mov.b64 %0, {%1,%2};" : "=l"(r) : "f"(lo), "f"(hi));
    return r;
}
__device__ __forceinline__ void upk2(unsigned long long v, float& lo, float& hi) {
    asm("mov.b64 {%0,%1}, %2;" : "=f"(lo), "=f"(hi) : "l"(v));
}
__device__ __forceinline__ void fma2(unsigned long long& d, unsigned long long a, unsigned long long b) {
    asm("fma.rn.f32x2 %0, %1, %2, %3;" : "=l"(d) : "l"(a), "l"(b), "l"(d));
}
__device__ __forceinline__ unsigned ld_relax(const unsigned* p) {
    unsigned v;
    asm volatile("ld.relaxed.gpu.global.u32 %0, [%1];" : "=r"(v) : "l"(p) : "memory");
    return v;
}
__device__ __forceinline__ unsigned ld_acq(const unsigned* p) {
    unsigned v;
    asm volatile("ld.acquire.gpu.global.u32 %0, [%1];" : "=r"(v) : "l"(p) : "memory");
    return v;
}
__device__ __forceinline__ void red_release(unsigned* p) {
    asm volatile("red.release.gpu.global.add.u32 [%0], %1;" :: "l"(p), "r"(1u) : "memory");
}

// sync-warp poll: lane<8 polls a[lane] >= tgtA ; 8<=lane<16 polls b2[lane-8] >= tgtB.
// Call from full warp (warp-uniform targets). Relaxed poll; acquire confirm.
__device__ __forceinline__ void poll_pair(const Ctr* a, unsigned tgtA,
                                          const Ctr* b2, unsigned tgtB, int lane) {
    const unsigned* cp;
    unsigned tgt;
    if (lane < 8)       { cp = &a[lane].v;      tgt = tgtA; }
    else if (lane < 16) { cp = &b2[lane - 8].v; tgt = tgtB; }
    else                { cp = &a[0].v;         tgt = 0u;   }
    for (;;) {
        unsigned v = ld_relax(cp);
        if (__all_sync(0xffffffffu, v >= tgt)) break;
    }
    ld_acq(cp);
}

// ---------------- kernel: zero counters ----------------
__global__ void k_zero_slots() {
    if (threadIdx.x < NGRP) { g_ctrA[threadIdx.x].v = 0u; g_ctrB[threadIdx.x].v = 0u; }
}

// ---------------- kernel: transpose x [b][t][j] -> xT [t][j][b] ----------------
__global__ void k_xT(const float* __restrict__ x) {
    __shared__ float sm[INP * 17];
    int t = blockIdx.x;
    int tid = threadIdx.x;
    #pragma unroll
    for (int bb = 0; bb < BATCH; bb++) {
        sm[tid * 17 + bb] = x[(size_t)bb * SEQ * INP + (size_t)t * INP + tid];
    }
    __syncthreads();
    float* dst = g_xT + (size_t)t * (INP * BATCH);
    #pragma unroll
    for (int k = 0; k < 16; k++) {
        int f = k * 256 + tid;            // f = j*16 + b
        dst[f] = sm[(f >> 4) * 17 + (f & 15)];
    }
}

// ---------------- kernel: build CSR ----------------
__global__ void k_csr(const float* __restrict__ wih, const float* __restrict__ whh) {
    int warp = threadIdx.x >> 5;
    int lane = threadIdx.x & 31;
    int gr = blockIdx.x * 8 + warp;
    if (gr >= 3 * HID) return;
    int m = gr / HID;
    int row = gr % HID;
    const float* src;
    int ncol;
    if (m == 0) { src = wih + (size_t)row * INP; ncol = INP; }
    else        { src = whh + ((size_t)(m - 1) * HID + row) * HID; ncol = HID; }
    int base = 0;
    for (int c0 = 0; c0 < ncol; c0 += 32) {
        float w = src[c0 + lane];
        unsigned mask = __ballot_sync(0xffffffffu, w != 0.0f);
        if (w != 0.0f) {
            int pos = base + __popc(mask & ((1u << lane) - 1u));
            if (pos < MAXNZ) {
                g_idx[m][row][pos] = (unsigned short)(c0 + lane);
                g_val[m][row][pos] = w;
            }
        }
        base += __popc(mask);
    }
    int cnt = base < MAXNZ ? base : MAXNZ;
    int rcnt = (cnt + 3) & ~3;
    for (int p = cnt + lane; p < rcnt; p += 32) {
        g_idx[m][row][p] = 0;
        g_val[m][row][p] = 0.0f;
    }
    if (lane == 0) g_cnt[m][row] = rcnt;
}

// ---------------- kernel: transpose out_w ----------------
__global__ void k_wT(const float* __restrict__ ow) {
    __shared__ float tl[32][33];
    int i0 = blockIdx.x * 32, o0 = blockIdx.y * 32;
    int tx = threadIdx.x, ty = threadIdx.y;
    tl[ty][tx] = ow[(size_t)(o0 + ty) * HID + i0 + tx];
    __syncthreads();
    g_WT[(size_t)(i0 + ty) * INP + o0 + tx] = tl[tx][ty];
}

// ---------------- persistent recurrence kernel ----------------
// CTAs 0..63: layer 0 ; CTAs 64..127: layer 1. 288 thr: warps 0-7 compute
// (one (i,b) element per thread), warp 8 = sync-only (arrive + poll).
// Arrivals sharded over 8 counters per layer (8 CTAs per counter address).
__global__ void __launch_bounds__(NTHR, 1) k_rnn() {
    __shared__ unsigned short sIdxA[16][MAXNZ];
    __shared__ float          sValA[16][MAXNZ];
    __shared__ unsigned short sIdxB[16][MAXNZ];
    __shared__ float          sValB[16][MAXNZ];
    __shared__ int sCntA[16], sCntB[16];

    int cta = blockIdx.x;
    int layer = cta >> 6;
    int gc = cta & 63;
    int r0 = gc * 16;
    int mA = (layer == 0) ? 0 : 2;       // layer0: ih0 ; layer1: hh1

    for (int e = threadIdx.x; e < 16 * MAXNZ; e += NTHR) {
        int rr = e >> 6, kk = e & 63;
        sIdxA[rr][kk] = g_idx[mA][r0 + rr][kk];
        sValA[rr][kk] = g_val[mA][r0 + rr][kk];
        if (layer == 0) {
            sIdxB[rr][kk] = g_idx[1][r0 + rr][kk];   // hh0
            sValB[rr][kk] = g_val[1][r0 + rr][kk];
        }
    }
    if (threadIdx.x < 16) {
        sCntA[threadIdx.x] = g_cnt[mA][r0 + threadIdx.x];
        sCntB[threadIdx.x] = (layer == 0) ? g_cnt[1][r0 + threadIdx.x] : 0;
    }
    __syncthreads();

    int warp = threadIdx.x >> 5;
    int lane = threadIdx.x & 31;
    bool is_sync = (warp == 8);
    int il = 2 * warp + (lane >> 4);     // 0..15 (compute warps)
    int b  = lane & 15;
    int i  = r0 + il;
    int cA = is_sync ? 0 : sCntA[il];
    int cB = is_sync ? 0 : sCntB[il];

    if (layer == 0) {
        // ======== layer 0 ========
        float ffx = 0.0f;
        if (!is_sync) {
            const float* xp = g_xT + b;
            float a0 = 0.0f, a1 = 0.0f;
            for (int k = 0; k < cA; k += 4) {
                int j0 = sIdxA[il][k], j1 = sIdxA[il][k+1], j2 = sIdxA[il][k+2], j3 = sIdxA[il][k+3];
                float v0 = sValA[il][k], v1 = sValA[il][k+1], v2 = sValA[il][k+2], v3 = sValA[il][k+3];
                a0 += v0 * __ldg(xp + (j0 << 4));
                a1 += v1 * __ldg(xp + (j1 << 4));
                a0 += v2 * __ldg(xp + (j2 << 4));
                a1 += v3 * __ldg(xp + (j3 << 4));
            }
            ffx = a0 + a1;
        }
        for (int t = 0; t < SEQ; t++) {
            if (t > 0) {
                if (is_sync) {
                    unsigned tgtA = (unsigned)(NGRP * t);           // h0(t-1) all visible
                    unsigned tgtB = (t >= HDEPTH) ? (unsigned)(NGRP * (t - HDEPTH + 1)) : 0u;
                    poll_pair(g_ctrA, tgtA, g_ctrB, tgtB, lane);    // ring slot free too
                }
                __syncthreads();
            }
            if (!is_sync) {
                float acc0 = SQRT10 + ffx, acc1 = 0.0f;
                if (t > 0) {
                    const float* hp = g_h0[(t - 1) & (HDEPTH - 1)] + b;
                    for (int k = 0; k < cB; k += 4) {
                        int j0 = sIdxB[il][k], j1 = sIdxB[il][k+1], j2 = sIdxB[il][k+2], j3 = sIdxB[il][k+3];
                        float v0 = sValB[il][k], v1 = sValB[il][k+1], v2 = sValB[il][k+2], v3 = sValB[il][k+3];
                        acc0 += v0 * __ldcg(hp + (j0 << 4));
                        acc1 += v1 * __ldcg(hp + (j1 << 4));
                        acc0 += v2 * __ldcg(hp + (j2 << 4));
                        acc1 += v3 * __ldcg(hp + (j3 << 4));
                    }
                }
                __stcg(&g_h0[t & (HDEPTH - 1)][i * 16 + b], fmaxf(acc0 + acc1, 0.0f));
            }
            __syncthreads();
            if (is_sync) {
                if (lane == 0) red_release(&g_ctrA[gc & (NGRP - 1)].v);
            } else if (t + 1 < SEQ) {
                // ffx(t+1) prefetch overlaps sync warp's release + next poll
                const float* xp = g_xT + (size_t)(t + 1) * (INP * BATCH) + b;
                float a0 = 0.0f, a1 = 0.0f;
                for (int k = 0; k < cA; k += 4) {
                    int j0 = sIdxA[il][k], j1 = sIdxA[il][k+1], j2 = sIdxA[il][k+2], j3 = sIdxA[il][k+3];
                    float v0 = sValA[il][k], v1 = sValA[il][k+1], v2 = sValA[il][k+2], v3 = sValA[il][k+3];
                    a0 += v0 * __ldg(xp + (j0 << 4));
                    a1 += v1 * __ldg(xp + (j1 << 4));
                    a0 += v2 * __ldg(xp + (j2 << 4));
                    a1 += v3 * __ldg(xp + (j3 << 4));
                }
                ffx = a0 + a1;
            }
        }
    } else {
        // ======== layer 1 ========
        for (int t = 0; t < SEQ; t++) {
            // stage 1: peers' h1(t-1) visible
            if (t > 0) {
                if (is_sync) poll_pair(g_ctrB, (unsigned)(NGRP * t), g_ctrB, 0u, lane);
                __syncthreads();
            }
            // stage 2: gather h1-recurrence while sync warp polls for h0(t)
            float accR0 = 0.0f, accR1 = 0.0f;
            if (is_sync) {
                poll_pair(g_ctrA, (unsigned)(NGRP * (t + 1)), g_ctrB, 0u, lane);
            } else if (t > 0) {
                const float* hp = g_outsT + (size_t)(t - 1) * (HID * BATCH) + b;
                for (int k = 0; k < cA; k += 4) {
                    int j0 = sIdxA[il][k], j1 = sIdxA[il][k+1], j2 = sIdxA[il][k+2], j3 = sIdxA[il][k+3];
                    float v0 = sValA[il][k], v1 = sValA[il][k+1], v2 = sValA[il][k+2], v3 = sValA[il][k+3];
                    accR0 += v0 * __ldcg(hp + (j0 << 4));
                    accR1 += v1 * __ldcg(hp + (j1 << 4));
                    accR0 += v2 * __ldcg(hp + (j2 << 4));
                    accR1 += v3 * __ldcg(hp + (j3 << 4));
                }
            }
            __syncthreads();
            // stage 3: gather h0(t), store h1(t)
            if (!is_sync) {
                float acc0 = SQRT10 + accR0, acc1 = accR1;
                const float* fp = g_h0[t & (HDEPTH - 1)] + b;
                for (int k = 0; k < cA; k += 4) {
                    int j0 = sIdxA[il][k], j1 = sIdxA[il][k+1], j2 = sIdxA[il][k+2], j3 = sIdxA[il][k+3];
                    float v0 = sValA[il][k], v1 = sValA[il][k+1], v2 = sValA[il][k+2], v3 = sValA[il][k+3];
                    acc0 += v0 * __ldcg(fp + (j0 << 4));
                    acc1 += v1 * __ldcg(fp + (j1 << 4));
                    acc0 += v2 * __ldcg(fp + (j2 << 4));
                    acc1 += v3 * __ldcg(fp + (j3 << 4));
                }
                __stcg(&g_outsT[(size_t)t * (HID * BATCH) + i * 16 + b], fmaxf(acc0 + acc1, 0.0f));
            }
            __syncthreads();
            if (is_sync && lane == 0) red_release(&g_ctrB[gc & (NGRP - 1)].v);
        }
    }
}

// ---------------- projection: out[b][t][o] = sum_i h1[t][i][b]*W[o][i] + bias[o] ----------------
__global__ void __launch_bounds__(256) k_proj(const float* __restrict__ ob, float* __restrict__ out) {
    __shared__ float sh[512 * BATCH];
    int t = blockIdx.x;
    int o = threadIdx.x;
    float bias = __ldg(ob + o);
    unsigned long long acc[8];
    #pragma unroll
    for (int j = 0; j < 8; j++) acc[j] = pk2(bias, bias);
    #pragma unroll
    for (int half = 0; half < 2; half++) {
        __syncthreads();
        const float* src = g_outsT + (size_t)t * (HID * BATCH) + half * (512 * BATCH);
        for (int e = threadIdx.x; e < 512 * BATCH; e += 256) sh[e] = src[e];
        __syncthreads();
        const float* wcol = g_WT + (size_t)(half * 512) * INP + o;
        #pragma unroll 2
        for (int i = 0; i < 512; i++) {
            float w = __ldg(wcol + (size_t)i * INP);
            unsigned long long wp = pk2(w, w);
            const unsigned long long* hp = (const unsigned long long*)(sh + i * BATCH);
            fma2(acc[0], hp[0], wp);
            fma2(acc[1], hp[1], wp);
            fma2(acc[2], hp[2], wp);
            fma2(acc[3], hp[3], wp);
            fma2(acc[4], hp[4], wp);
            fma2(acc[5], hp[5], wp);
            fma2(acc[6], hp[6], wp);
            fma2(acc[7], hp[7], wp);
        }
    }
    #pragma unroll
    for (int j = 0; j < 8; j++) {
        float lo, hi;
        upk2(acc[j], lo, hi);
        out[((size_t)(2 * j)     * SEQ + t) * INP + o] = lo;
        out[((size_t)(2 * j + 1) * SEQ + t) * INP + o] = hi;
    }
}

// ---------------- final hidden state h_T [l][b][i] ----------------
__global__ void k_ht(float* __restrict__ out) {
    int e = blockIdx.x * blockDim.x + threadIdx.x;
    if (e >= HT_ELEMS) return;
    int l = e / (BATCH * HID);
    int r = e % (BATCH * HID);
    int b = r / HID;
    int i = r % HID;
    float v;
    if (l == 0) v = g_h0[(SEQ - 1) & (HDEPTH - 1)][i * 16 + b];
    else        v = g_outsT[(size_t)(SEQ - 1) * (HID * BATCH) + i * 16 + b];
    out[(size_t)OUT_MAIN + e] = v;
}

// ---------------- launch ----------------
// k_rnn at the same launch index as R9/R11 so ncu (-s 5 -c 1) captures it.
extern "C" void kernel_launch(void* const* d_in, const int* in_sizes, int n_in,
                              void* d_out, int out_size) {
    const float* x   = (const float*)d_in[0];
    const float* wih = (const float*)d_in[1];
    const float* whh = (const float*)d_in[2];
    const float* ow  = (const float*)d_in[3];
    const float* ob  = (const float*)d_in[4];
    float* out = (float*)d_out;

    k_zero_slots<<<1, 32>>>();
    k_xT<<<SEQ, 256>>>(x);
    k_csr<<<(3 * HID) / 8, 256>>>(wih, whh);
    k_rnn<<<NCTA, NTHR>>>();
    k_wT<<<dim3(HID / 32, INP / 32), dim3(32, 32)>>>(ow);
    k_proj<<<SEQ, 256>>>(ob, out);
    if (out_size >= OUT_MAIN + HT_ELEMS) {
        k_ht<<<(HT_ELEMS + 511) / 512, 512>>>(out);
    }
}